// round 5
// baseline (speedup 1.0000x reference)
#include <cuda_runtime.h>
#include <cuda_bf16.h>
#include <cstdint>
#include <math.h>

#define T_STEPS 1024
#define BATCH   64
#define UDIM    256
#define FDIM    128

// 64MB scratch for h[b][t][u] (device global: allowed, no runtime alloc)
__device__ float g_h[(size_t)BATCH * T_STEPS * UDIM];

// ---------------- helpers ----------------
__device__ __forceinline__ void fma2(unsigned long long &d, unsigned long long a, unsigned long long b) {
    asm("fma.rn.f32x2 %0, %1, %2, %0;" : "+l"(d) : "l"(a), "l"(b));
}
__device__ __forceinline__ float lo32(unsigned long long v){ return __uint_as_float((unsigned)(v & 0xffffffffull)); }
__device__ __forceinline__ float hi32(unsigned long long v){ return __uint_as_float((unsigned)(v >> 32)); }
__device__ __forceinline__ unsigned long long packf2(float lo, float hi){
    return (unsigned long long)__float_as_uint(lo) | ((unsigned long long)__float_as_uint(hi) << 32);
}
__device__ __forceinline__ uint32_t smem_u32(const void* p) {
    return (uint32_t)__cvta_generic_to_shared(p);
}
__device__ __forceinline__ uint32_t mapa_u32(uint32_t a, uint32_t peer) {
    uint32_t d;
    asm("mapa.shared::cluster.u32 %0, %1, %2;" : "=r"(d) : "r"(a), "r"(peer));
    return d;
}
__device__ __forceinline__ void mbar_init(uint32_t addr, uint32_t count) {
    asm volatile("mbarrier.init.shared.b64 [%0], %1;" :: "r"(addr), "r"(count) : "memory");
}
__device__ __forceinline__ void mbar_arrive_local(uint32_t addr) {
    asm volatile("mbarrier.arrive.release.cta.shared::cta.b64 _, [%0];" :: "r"(addr) : "memory");
}
__device__ __forceinline__ void mbar_arrive_remote(uint32_t addr) {
    asm volatile("mbarrier.arrive.release.cluster.shared::cluster.b64 _, [%0];" :: "r"(addr) : "memory");
}
__device__ __forceinline__ void mbar_wait(uint32_t addr, uint32_t parity) {
    asm volatile(
        "{\n\t"
        ".reg .pred P;\n\t"
        "WAIT_%=:\n\t"
        "mbarrier.try_wait.parity.acquire.cluster.shared::cta.b64 P, [%0], %1, 0x989680;\n\t"
        "@P bra DONE_%=;\n\t"
        "bra WAIT_%=;\n\t"
        "DONE_%=:\n\t"
        "}"
        :: "r"(addr), "r"(parity) : "memory");
}
__device__ __forceinline__ void dsmem_st_f32(uint32_t addr, float v) {
    asm volatile("st.shared::cluster.f32 [%0], %1;" :: "r"(addr), "f"(v) : "memory");
}
// branchless tanh: 1 - 2/(exp(2x)+1), ex2.approx + rcp.approx (~1e-7 abs err)
__device__ __forceinline__ float fast_tanh(float x) {
    float z = x * 2.8853900817779268f;   // 2*log2(e)
    float e;
    asm("ex2.approx.f32 %0, %1;" : "=f"(e) : "f"(z));
    float d = e + 1.0f;
    float r;
    asm("rcp.approx.f32 %0, %1;" : "=f"(r) : "f"(d));
    return fmaf(-2.0f, r, 1.0f);
}

// state buffer layout: column c lives at index c + (c>>7)*4 (16B pad between
// halves so the two per-warp broadcast addresses hit disjoint banks)
#define SBUF_STRIDE 264
__device__ __forceinline__ int sidx(int c){ return c + ((c >> 7) << 2); }

// ============================================================
// Phase 1: g_h[b][t][u] = sum_f inputs[b,t,f] * R[f,u]
// ============================================================
__global__ __launch_bounds__(256)
void p1_gemm(const float* __restrict__ x, const float* __restrict__ R) {
    extern __shared__ unsigned char smraw[];
    float* xs = (float*)smraw;                                          // 32KB
    unsigned long long* Rp = (unsigned long long*)(smraw + 64*128*4);   // 64KB

    const int tid = threadIdx.x;
    const int c = blockIdx.x;
    const int rowblk = c >> 1, uh = c & 1;
    const int m0 = rowblk * 64, ub = uh * 128;

    {
        const float4* xg = (const float4*)(x + (size_t)m0 * FDIM);
        float4* xs4 = (float4*)xs;
        #pragma unroll
        for (int i = 0; i < 8; i++) xs4[tid + 256*i] = xg[tid + 256*i];
    }
    for (int i = tid; i < 64*128; i += 256) {
        int k2 = i >> 7; int u = (i & 127) + ub;
        Rp[i] = packf2(R[(size_t)(2*k2) * UDIM + u], R[(size_t)(2*k2+1) * UDIM + u]);
    }
    __syncthreads();

    const int cg = tid & 31, tr = tid >> 5;
    const int u0 = cg * 4, r0 = tr * 8;

    unsigned long long acc[8][4];
    #pragma unroll
    for (int a = 0; a < 8; a++)
        #pragma unroll
        for (int bb = 0; bb < 4; bb++) acc[a][bb] = 0ULL;

    #pragma unroll 8
    for (int k2 = 0; k2 < 64; k2++) {
        const ulonglong2* rp2 = (const ulonglong2*)(Rp + k2*128 + u0);
        ulonglong2 v0 = rp2[0], v1 = rp2[1];
        #pragma unroll
        for (int rr = 0; rr < 8; rr++) {
            unsigned long long xp = *(const unsigned long long*)(xs + (r0+rr)*FDIM + 2*k2);
            fma2(acc[rr][0], xp, v0.x);
            fma2(acc[rr][1], xp, v0.y);
            fma2(acc[rr][2], xp, v1.x);
            fma2(acc[rr][3], xp, v1.y);
        }
    }

    #pragma unroll
    for (int rr = 0; rr < 8; rr++) {
        int m = m0 + r0 + rr;   // m = b*1024 + t -> [B][T][U] directly
        float4 o;
        o.x = lo32(acc[rr][0]) + hi32(acc[rr][0]);
        o.y = lo32(acc[rr][1]) + hi32(acc[rr][1]);
        o.z = lo32(acc[rr][2]) + hi32(acc[rr][2]);
        o.w = lo32(acc[rr][3]) + hi32(acc[rr][3]);
        *(float4*)(g_h + (size_t)m * UDIM + ub + u0) = o;
    }
}

// ============================================================
// Phase 2: recurrence. 64 clusters x 2 CTAs; one batch per cluster.
// CTA rank r owns output columns [r*128, r*128+128), W column-segment in regs.
// Thread map: warp w, lane: kh = lane>>4, l = lane&15.
//   column jloc = w*16 + l (0..127), K range [kh*128, kh*128+128).
// Per step: 64 FFMA2 -> shfl.xor(16) reduce -> fast tanh (both halves) ->
//   lanes<16: own-smem STS; lanes>=16: DSMEM store to peer
//   __syncwarp -> lane0: local arrive, lane16: remote arrive  (16 arrivals
//   total on each mbar instead of 256 -> kills mbar serialization)
//   -> output STG (off chain) -> mbar wait (parity t&1).
// ============================================================
__global__ __launch_bounds__(256, 1) __cluster_dims__(2, 1, 1)
void p2_rnn(const float* __restrict__ W, const float* __restrict__ bias,
            const float* __restrict__ x0, float* __restrict__ out) {
    __shared__ __align__(16) float sbuf[2][SBUF_STRIDE];
    __shared__ __align__(8) unsigned long long mbar;

    const int tid  = threadIdx.x;
    uint32_t rank;
    asm("mov.u32 %0, %%cluster_ctarank;" : "=r"(rank));
    const int b    = blockIdx.x >> 1;
    const int w    = tid >> 5;
    const int lane = tid & 31;
    const int kh   = lane >> 4;
    const int jloc = w * 16 + (lane & 15);
    const int jg   = (int)rank * 128 + jloc;
    const int k0   = kh * 128;

    // W column segment, packed f32x2 over k-pairs: 64 x u64 = 128 regs
    unsigned long long wp[64];
    #pragma unroll
    for (int m = 0; m < 64; m++) {
        wp[m] = packf2(W[(size_t)(k0 + 2*m)     * UDIM + jg],
                       W[(size_t)(k0 + 2*m + 1) * UDIM + jg]);
    }

    const float* hptr  = g_h + (size_t)b * T_STEPS * UDIM + jg;
    float*       obase = out + (size_t)b * UDIM + jg;
    const float  bias_j = bias[jg];
    float hA = hptr[0];
    float hB = hptr[UDIM];

    if (tid < UDIM) sbuf[0][sidx(tid)] = x0[tid];
    if (tid == 0) mbar_init(smem_u32(&mbar), 16);   // 8 local + 8 remote warp-arrives
    __syncthreads();
    asm volatile("barrier.cluster.arrive.aligned;" ::: "memory");
    asm volatile("barrier.cluster.wait.aligned;"   ::: "memory");

    const uint32_t mloc = smem_u32(&mbar);
    const uint32_t pr   = rank ^ 1u;
    const uint32_t psb0 = mapa_u32(smem_u32(&sbuf[0][0]), pr);
    const uint32_t psb1 = mapa_u32(smem_u32(&sbuf[1][0]), pr);
    const uint32_t pmb  = mapa_u32(mloc, pr);
    const uint32_t pdst_off = (uint32_t)sidx(jg) * 4u;

    for (int t = 0; t < T_STEPS; t++) {
        const int p = t & 1;
        const float* sb = &sbuf[p][sidx(k0)];

        // prefetch h for t+2 early (independent of this step's chain)
        float hC = 0.f;
        if (t + 2 < T_STEPS) hC = __ldcs(hptr + (size_t)(t + 2) * UDIM);

        unsigned long long a0 = 0ULL, a1 = 0ULL, a2 = 0ULL, a3 = 0ULL;
        #pragma unroll
        for (int m2 = 0; m2 < 16; m2++) {
            ulonglong2 s0 = *(const ulonglong2*)(sb + 8*m2);
            ulonglong2 s1 = *(const ulonglong2*)(sb + 8*m2 + 4);
            fma2(a0, s0.x, wp[4*m2 + 0]);
            fma2(a1, s0.y, wp[4*m2 + 1]);
            fma2(a2, s1.x, wp[4*m2 + 2]);
            fma2(a3, s1.y, wp[4*m2 + 3]);
        }
        float partial = ((lo32(a0) + hi32(a0)) + (lo32(a1) + hi32(a1)))
                      + ((lo32(a2) + hi32(a2)) + (lo32(a3) + hi32(a3)));
        // cross-K-half reduce inside the warp
        float tot = partial + __shfl_xor_sync(0xffffffffu, partial, 16);
        float val = fast_tanh(hA + tot + bias_j);

        if (lane < 16) {
            sbuf[p ^ 1][sidx(jg)] = val;                    // own state buffer
        } else {
            dsmem_st_f32((p ? psb0 : psb1) + pdst_off, val); // peer state buffer
        }
        __syncwarp();   // intra-warp happens-before: one lane's release covers all stores
        if (lane == 0)       mbar_arrive_local(mloc);
        else if (lane == 16) mbar_arrive_remote(pmb);

        if (lane < 16) obase[(size_t)t * BATCH * UDIM] = val;  // output, off chain

        mbar_wait(mloc, (uint32_t)(t & 1));

        hA = hB; hB = hC;
    }

    asm volatile("barrier.cluster.arrive.aligned;" ::: "memory");
    asm volatile("barrier.cluster.wait.aligned;"   ::: "memory");
}

extern "C" void kernel_launch(void* const* d_in, const int* in_sizes, int n_in,
                              void* d_out, int out_size) {
    const float* x    = (const float*)d_in[0];  // [B, T, F]
    const float* R    = (const float*)d_in[1];  // [F, U]
    const float* W    = (const float*)d_in[2];  // [U, U]
    const float* bias = (const float*)d_in[3];  // [U]
    const float* x0   = (const float*)d_in[4];  // [U]
    float* out = (float*)d_out;                 // [T, B, U]

    cudaFuncSetAttribute(p1_gemm, cudaFuncAttributeMaxDynamicSharedMemorySize, 98304);
    p1_gemm<<<2048, 256, 98304>>>(x, R);
    p2_rnn<<<128, 256>>>(W, bias, x0, out);
}

// round 6
// speedup vs baseline: 1.5701x; 1.5701x over previous
#include <cuda_runtime.h>
#include <cuda_bf16.h>
#include <cstdint>
#include <math.h>

#define T_STEPS 1024
#define BATCH   64
#define UDIM    256
#define FDIM    128

// 64MB scratch for h[b][t][u] (device global: allowed, no runtime alloc)
__device__ float g_h[(size_t)BATCH * T_STEPS * UDIM];

// ---------------- helpers ----------------
__device__ __forceinline__ void fma2(unsigned long long &d, unsigned long long a, unsigned long long b) {
    asm("fma.rn.f32x2 %0, %1, %2, %0;" : "+l"(d) : "l"(a), "l"(b));
}
__device__ __forceinline__ float lo32(unsigned long long v){ return __uint_as_float((unsigned)(v & 0xffffffffull)); }
__device__ __forceinline__ float hi32(unsigned long long v){ return __uint_as_float((unsigned)(v >> 32)); }
__device__ __forceinline__ unsigned long long packf2(float lo, float hi){
    return (unsigned long long)__float_as_uint(lo) | ((unsigned long long)__float_as_uint(hi) << 32);
}
__device__ __forceinline__ uint32_t smem_u32(const void* p) {
    return (uint32_t)__cvta_generic_to_shared(p);
}
__device__ __forceinline__ uint32_t mapa_u32(uint32_t a, uint32_t peer) {
    uint32_t d;
    asm("mapa.shared::cluster.u32 %0, %1, %2;" : "=r"(d) : "r"(a), "r"(peer));
    return d;
}
__device__ __forceinline__ void mbar_init(uint32_t addr, uint32_t count) {
    asm volatile("mbarrier.init.shared.b64 [%0], %1;" :: "r"(addr), "r"(count) : "memory");
}
__device__ __forceinline__ void mbar_arrive_local(uint32_t addr) {
    asm volatile("mbarrier.arrive.release.cta.shared::cta.b64 _, [%0];" :: "r"(addr) : "memory");
}
__device__ __forceinline__ void mbar_arrive_remote(uint32_t addr) {
    asm volatile("mbarrier.arrive.release.cluster.shared::cluster.b64 _, [%0];" :: "r"(addr) : "memory");
}
__device__ __forceinline__ void mbar_wait(uint32_t addr, uint32_t parity) {
    asm volatile(
        "{\n\t"
        ".reg .pred P;\n\t"
        "WAIT_%=:\n\t"
        "mbarrier.try_wait.parity.acquire.cluster.shared::cta.b64 P, [%0], %1, 0x989680;\n\t"
        "@P bra DONE_%=;\n\t"
        "bra WAIT_%=;\n\t"
        "DONE_%=:\n\t"
        "}"
        :: "r"(addr), "r"(parity) : "memory");
}
__device__ __forceinline__ void dsmem_st_f32(uint32_t addr, float v) {
    asm volatile("st.shared::cluster.f32 [%0], %1;" :: "r"(addr), "f"(v) : "memory");
}
// branchless tanh: 1 - 2/(exp(2x)+1), ex2.approx + rcp.approx (~1e-7 abs err)
__device__ __forceinline__ float fast_tanh(float x) {
    float z = x * 2.8853900817779268f;   // 2*log2(e)
    float e;
    asm("ex2.approx.f32 %0, %1;" : "=f"(e) : "f"(z));
    float d = e + 1.0f;
    float r;
    asm("rcp.approx.f32 %0, %1;" : "=f"(r) : "f"(d));
    return fmaf(-2.0f, r, 1.0f);
}

// state buffer layout: quarter q (64 cols) padded by 16B so the 4 per-warp
// broadcast groups (one per K-quarter) hit disjoint bank sets.
#define SBUF_STRIDE 272
__device__ __forceinline__ int sidx4(int c){ return c + ((c >> 6) << 2); }

// ============================================================
// Phase 1: g_h[b][t][u] = sum_f inputs[b,t,f] * R[f,u]
// ============================================================
__global__ __launch_bounds__(256)
void p1_gemm(const float* __restrict__ x, const float* __restrict__ R) {
    extern __shared__ unsigned char smraw[];
    float* xs = (float*)smraw;                                          // 32KB
    unsigned long long* Rp = (unsigned long long*)(smraw + 64*128*4);   // 64KB

    const int tid = threadIdx.x;
    const int c = blockIdx.x;
    const int rowblk = c >> 1, uh = c & 1;
    const int m0 = rowblk * 64, ub = uh * 128;

    {
        const float4* xg = (const float4*)(x + (size_t)m0 * FDIM);
        float4* xs4 = (float4*)xs;
        #pragma unroll
        for (int i = 0; i < 8; i++) xs4[tid + 256*i] = xg[tid + 256*i];
    }
    for (int i = tid; i < 64*128; i += 256) {
        int k2 = i >> 7; int u = (i & 127) + ub;
        Rp[i] = packf2(R[(size_t)(2*k2) * UDIM + u], R[(size_t)(2*k2+1) * UDIM + u]);
    }
    __syncthreads();

    const int cg = tid & 31, tr = tid >> 5;
    const int u0 = cg * 4, r0 = tr * 8;

    unsigned long long acc[8][4];
    #pragma unroll
    for (int a = 0; a < 8; a++)
        #pragma unroll
        for (int bb = 0; bb < 4; bb++) acc[a][bb] = 0ULL;

    #pragma unroll 8
    for (int k2 = 0; k2 < 64; k2++) {
        const ulonglong2* rp2 = (const ulonglong2*)(Rp + k2*128 + u0);
        ulonglong2 v0 = rp2[0], v1 = rp2[1];
        #pragma unroll
        for (int rr = 0; rr < 8; rr++) {
            unsigned long long xp = *(const unsigned long long*)(xs + (r0+rr)*FDIM + 2*k2);
            fma2(acc[rr][0], xp, v0.x);
            fma2(acc[rr][1], xp, v0.y);
            fma2(acc[rr][2], xp, v1.x);
            fma2(acc[rr][3], xp, v1.y);
        }
    }

    #pragma unroll
    for (int rr = 0; rr < 8; rr++) {
        int m = m0 + r0 + rr;   // m = b*1024 + t -> [B][T][U] directly
        float4 o;
        o.x = lo32(acc[rr][0]) + hi32(acc[rr][0]);
        o.y = lo32(acc[rr][1]) + hi32(acc[rr][1]);
        o.z = lo32(acc[rr][2]) + hi32(acc[rr][2]);
        o.w = lo32(acc[rr][3]) + hi32(acc[rr][3]);
        *(float4*)(g_h + (size_t)m * UDIM + ub + u0) = o;
    }
}

// ============================================================
// Phase 2: recurrence. 64 clusters x 2 CTAs; one batch per cluster.
// CTA rank r owns output columns [r*128, r*128+128).
// Thread map (warp w, lane l): quarter q = l>>3, cols jA = w*16+(l&7), jB=jA+8,
// K range [q*64, q*64+64). Each thread: 16 LDS.128 feed 64 FFMA2 (2 cols).
// Reduce over q: shfl.xor(8) + shfl.xor(16). All 4 q-copies hold the sums.
// Epilogue split by q: q0 = STS own sbuf + local arrive; q1 = DSMEM to peer +
// remote arrive; q2/q3 = output STG (off-chain). Per-lane arrives (proven in
// R3; R5's aggregation regressed). mbar count = 64 local + 64 remote = 128.
// ============================================================
__global__ __launch_bounds__(256, 1) __cluster_dims__(2, 1, 1)
void p2_rnn(const float* __restrict__ W, const float* __restrict__ bias,
            const float* __restrict__ x0, float* __restrict__ out) {
    __shared__ __align__(16) float sbuf[2][SBUF_STRIDE];
    __shared__ __align__(8) unsigned long long mbar;

    const int tid  = threadIdx.x;
    uint32_t rank;
    asm("mov.u32 %0, %%cluster_ctarank;" : "=r"(rank));
    const int b    = blockIdx.x >> 1;
    const int w    = tid >> 5;
    const int l    = tid & 31;
    const int q    = l >> 3;
    const int jA   = w * 16 + (l & 7);
    const int jgA  = (int)rank * 128 + jA;
    const int jgB  = jgA + 8;
    const int k0   = q * 64;

    // W segments for 2 columns x quarter-K, packed f32x2: 64 u64 = 128 regs
    unsigned long long wpA[32], wpB[32];
    #pragma unroll
    for (int m = 0; m < 32; m++) {
        wpA[m] = packf2(W[(size_t)(k0 + 2*m)     * UDIM + jgA],
                        W[(size_t)(k0 + 2*m + 1) * UDIM + jgA]);
        wpB[m] = packf2(W[(size_t)(k0 + 2*m)     * UDIM + jgB],
                        W[(size_t)(k0 + 2*m + 1) * UDIM + jgB]);
    }

    const float* hpA = g_h + (size_t)b * T_STEPS * UDIM + jgA;
    const float* hpB = g_h + (size_t)b * T_STEPS * UDIM + jgB;
    float* outA = out + (size_t)b * UDIM + jgA;
    float* outB = out + (size_t)b * UDIM + jgB;
    const float biasA = bias[jgA];
    const float biasB = bias[jgB];
    float hA0 = hpA[0], hA1 = hpA[UDIM];
    float hB0 = hpB[0], hB1 = hpB[UDIM];

    if (tid < UDIM) sbuf[0][sidx4(tid)] = x0[tid];
    if (tid == 0) mbar_init(smem_u32(&mbar), 128);
    __syncthreads();
    asm volatile("barrier.cluster.arrive.aligned;" ::: "memory");
    asm volatile("barrier.cluster.wait.aligned;"   ::: "memory");

    const uint32_t mloc = smem_u32(&mbar);
    const uint32_t pr   = rank ^ 1u;
    const uint32_t psb0 = mapa_u32(smem_u32(&sbuf[0][0]), pr);
    const uint32_t psb1 = mapa_u32(smem_u32(&sbuf[1][0]), pr);
    const uint32_t pmb  = mapa_u32(mloc, pr);
    const uint32_t poffA = (uint32_t)sidx4(jgA) * 4u;
    const uint32_t poffB = (uint32_t)sidx4(jgB) * 4u;

    #pragma unroll 2
    for (int t = 0; t < T_STEPS; t++) {
        const int p = t & 1;
        const float* sb = &sbuf[p][sidx4(k0)];

        // prefetch h for t+2 early (independent of this step's chain)
        float hA2 = 0.f, hB2 = 0.f;
        if (t + 2 < T_STEPS) {
            hA2 = __ldcs(hpA + (size_t)(t + 2) * UDIM);
            hB2 = __ldcs(hpB + (size_t)(t + 2) * UDIM);
        }

        unsigned long long aA0 = 0ULL, aA1 = 0ULL, aB0 = 0ULL, aB1 = 0ULL;
        #pragma unroll
        for (int i = 0; i < 8; i++) {
            ulonglong2 s0 = *(const ulonglong2*)(sb + 8*i);
            ulonglong2 s1 = *(const ulonglong2*)(sb + 8*i + 4);
            fma2(aA0, s0.x, wpA[4*i + 0]);
            fma2(aB0, s0.x, wpB[4*i + 0]);
            fma2(aA1, s0.y, wpA[4*i + 1]);
            fma2(aB1, s0.y, wpB[4*i + 1]);
            fma2(aA0, s1.x, wpA[4*i + 2]);
            fma2(aB0, s1.x, wpB[4*i + 2]);
            fma2(aA1, s1.y, wpA[4*i + 3]);
            fma2(aB1, s1.y, wpB[4*i + 3]);
        }
        float pA = (lo32(aA0) + hi32(aA0)) + (lo32(aA1) + hi32(aA1));
        float pB = (lo32(aB0) + hi32(aB0)) + (lo32(aB1) + hi32(aB1));

        // reduce across the 4 K-quarters (lanes xor 8, then xor 16)
        pA += __shfl_xor_sync(0xffffffffu, pA, 8);
        pB += __shfl_xor_sync(0xffffffffu, pB, 8);
        pA += __shfl_xor_sync(0xffffffffu, pA, 16);
        pB += __shfl_xor_sync(0xffffffffu, pB, 16);

        float valA = fast_tanh(hA0 + pA + biasA);
        float valB = fast_tanh(hB0 + pB + biasB);

        if (l < 16) {
            if (l < 8) {
                // q0: own state buffer (next parity) + local arrive
                sbuf[p ^ 1][sidx4(jgA)] = valA;
                sbuf[p ^ 1][sidx4(jgB)] = valB;
                mbar_arrive_local(mloc);
            } else {
                // q1: peer state buffer via DSMEM + remote arrive
                const uint32_t pb = p ? psb0 : psb1;
                dsmem_st_f32(pb + poffA, valA);
                dsmem_st_f32(pb + poffB, valB);
                mbar_arrive_remote(pmb);
            }
        } else {
            // q2/q3: output [T][B][U], fully off the inter-CTA chain
            if (l < 24) outA[(size_t)t * BATCH * UDIM] = valA;
            else        outB[(size_t)t * BATCH * UDIM] = valB;
        }

        mbar_wait(mloc, (uint32_t)(t & 1));

        hA0 = hA1; hA1 = hA2;
        hB0 = hB1; hB1 = hB2;
    }

    asm volatile("barrier.cluster.arrive.aligned;" ::: "memory");
    asm volatile("barrier.cluster.wait.aligned;"   ::: "memory");
}

extern "C" void kernel_launch(void* const* d_in, const int* in_sizes, int n_in,
                              void* d_out, int out_size) {
    const float* x    = (const float*)d_in[0];  // [B, T, F]
    const float* R    = (const float*)d_in[1];  // [F, U]
    const float* W    = (const float*)d_in[2];  // [U, U]
    const float* bias = (const float*)d_in[3];  // [U]
    const float* x0   = (const float*)d_in[4];  // [U]
    float* out = (float*)d_out;                 // [T, B, U]

    cudaFuncSetAttribute(p1_gemm, cudaFuncAttributeMaxDynamicSharedMemorySize, 98304);
    p1_gemm<<<2048, 256, 98304>>>(x, R);
    p2_rnn<<<128, 256>>>(W, bias, x0, out);
}